// round 1
// baseline (speedup 1.0000x reference)
#include <cuda_runtime.h>
#include <math.h>

#define NU 50000
#define NI 30000
#define NN 80000
#define DD 64

#define NNZ_UI 1000000
#define NNZ_R  800000
#define NNZ_II 300000

// ---------------- scratch (static device globals; no allocs allowed) ----------
__device__ float g_cat0[NN * DD];
__device__ float g_cat1[NN * DD];
__device__ float g_cat2[NN * DD];
__device__ float g_img_ui[NN * DD];
__device__ float g_txt_ui[NN * DD];
__device__ float g_tmp0[NI * DD];
__device__ float g_tmp1[NI * DD];
__device__ float g_feat[NI * DD];

__device__ __forceinline__ float lrelu(float x) { return x >= 0.f ? x : 0.01f * x; }

// ---------------- elementwise helpers ----------------------------------------
__global__ void zero_kernel(float* __restrict__ p, int n4) {
    int i = blockIdx.x * blockDim.x + threadIdx.x;
    if (i < n4) reinterpret_cast<float4*>(p)[i] = make_float4(0.f, 0.f, 0.f, 0.f);
}

__global__ void copy_kernel(float* __restrict__ dst, const float* __restrict__ src, int n4) {
    int i = blockIdx.x * blockDim.x + threadIdx.x;
    if (i < n4) reinterpret_cast<float4*>(dst)[i] = reinterpret_cast<const float4*>(src)[i];
}

__global__ void mean3_kernel(const float* __restrict__ a, const float* __restrict__ b,
                             const float* __restrict__ c, float* __restrict__ out, int n4) {
    int i = blockIdx.x * blockDim.x + threadIdx.x;
    if (i >= n4) return;
    float4 A = reinterpret_cast<const float4*>(a)[i];
    float4 B = reinterpret_cast<const float4*>(b)[i];
    float4 C = reinterpret_cast<const float4*>(c)[i];
    const float s = 1.f / 3.f;
    reinterpret_cast<float4*>(out)[i] =
        make_float4((A.x + B.x + C.x) * s, (A.y + B.y + C.y) * s,
                    (A.z + B.z + C.z) * s, (A.w + B.w + C.w) * s);
}

// ---------------- SpMM: out[rows[e]] += vals[e] * x[cols[e]] ------------------
// 16 threads per edge, each handles one float4 (D=64 = 16 x float4).
__global__ void spmm_kernel(const int* __restrict__ rows, const int* __restrict__ cols,
                            const float* __restrict__ vals, const float* __restrict__ x,
                            float* __restrict__ out, int nnz) {
    int t = blockIdx.x * blockDim.x + threadIdx.x;
    int e = t >> 4;
    if (e >= nnz) return;
    int j = t & 15;
    int c = __ldg(&cols[e]);
    int r = __ldg(&rows[e]);
    float v = __ldg(&vals[e]);
    float4 xv = __ldg(reinterpret_cast<const float4*>(x) + (size_t)c * 16 + j);
    float* dst = out + (size_t)r * 64 + j * 4;
    asm volatile("red.global.add.v4.f32 [%0], {%1, %2, %3, %4};"
                 :: "l"(dst), "f"(v * xv.x), "f"(v * xv.y), "f"(v * xv.z), "f"(v * xv.w)
                 : "memory");
}

// ---------------- projection GEMM + BN + leaky_relu ---------------------------
// out[r,d] = lrelu( (x[r,:] @ W[:,d] + b[d]) * (g[d]/sqrt(1+eps)) + beta[d] )
// Block: 256 threads = 32 rows x 8 col-groups (8 cols each). K tiled by 64.
template <int F>
__global__ void proj_kernel(const float* __restrict__ x, const float* __restrict__ W,
                            const float* __restrict__ b, const float* __restrict__ g,
                            const float* __restrict__ beta, float* __restrict__ out) {
    __shared__ float  sX[32][68];       // padded: rows hit distinct banks
    __shared__ float4 sW[64][16];       // W chunk [64 k][64 cols as 16 float4]

    int tid = threadIdx.x;
    int cg  = tid & 7;        // col group: cols cg*8 .. cg*8+7
    int row = tid >> 3;       // 0..31
    int r0  = blockIdx.x * 32;

    float acc[8];
#pragma unroll
    for (int i = 0; i < 8; i++) acc[i] = 0.f;

    for (int kc = 0; kc < F; kc += 64) {
        // stage X tile: 32 rows x 64 k
        {
            int lr = tid >> 3;
            int lc = (tid & 7) * 8;
            int gr = r0 + lr;
            float4 a = make_float4(0.f, 0.f, 0.f, 0.f), bb = a;
            if (gr < NI) {
                const float* src = x + (size_t)gr * F + kc + lc;
                a  = *reinterpret_cast<const float4*>(src);
                bb = *reinterpret_cast<const float4*>(src + 4);
            }
            *reinterpret_cast<float4*>(&sX[lr][lc])     = a;
            *reinterpret_cast<float4*>(&sX[lr][lc + 4]) = bb;
        }
        // stage W tile: 64 k x 64 cols
#pragma unroll
        for (int i = 0; i < 4; i++) {
            int idx = tid + i * 256;        // float4 index
            int wk  = idx >> 4;
            int wc  = idx & 15;
            sW[wk][wc] = *reinterpret_cast<const float4*>(&W[(size_t)(kc + wk) * 64 + wc * 4]);
        }
        __syncthreads();

#pragma unroll
        for (int k = 0; k < 64; k++) {
            float  xv = sX[row][k];
            float4 w0 = sW[k][cg * 2];
            float4 w1 = sW[k][cg * 2 + 1];
            acc[0] += xv * w0.x; acc[1] += xv * w0.y; acc[2] += xv * w0.z; acc[3] += xv * w0.w;
            acc[4] += xv * w1.x; acc[5] += xv * w1.y; acc[6] += xv * w1.z; acc[7] += xv * w1.w;
        }
        __syncthreads();
    }

    int r = r0 + row;
    if (r < NI) {
        const float rs = rsqrtf(1.f + 1e-5f);
        int dbase = cg * 8;
#pragma unroll
        for (int j = 0; j < 8; j++) {
            int d = dbase + j;
            float v = acc[j] + __ldg(&b[d]);
            v = v * (__ldg(&g[d]) * rs) + __ldg(&beta[d]);
            out[(size_t)r * 64 + d] = lrelu(v);
        }
    }
}

// ---------------- gate: it[r,d] = item_emb[r,d] * sigmoid(feat[r,:]@Wg[:,d]+bg[d])
__global__ void gate_kernel(const float* __restrict__ feat, const float* __restrict__ item_emb,
                            const float* __restrict__ Wg, const float* __restrict__ bg,
                            float* __restrict__ out) {
    int r = blockIdx.x;
    int d = threadIdx.x;   // 64 threads
    __shared__ float sf[64];
    sf[d] = feat[(size_t)r * 64 + d];
    __syncthreads();
    float acc = __ldg(&bg[d]);
#pragma unroll 8
    for (int k = 0; k < 64; k++) acc += sf[k] * __ldg(&Wg[k * 64 + d]);
    float sig = 1.f / (1.f + __expf(-acc));
    out[(size_t)r * 64 + d] = item_emb[(size_t)r * 64 + d] * sig;
}

// ---------------- attention scores + softmax + combine (writes out[1..3]) ----
__global__ void att_fuse_kernel(const float* __restrict__ img_ui, const float* __restrict__ txt_ui,
                                const float* __restrict__ W1, const float* __restrict__ b1,
                                const float* __restrict__ w2, float* __restrict__ out) {
    int r = blockIdx.x;
    int d = threadIdx.x;   // 64 threads
    __shared__ float sei[64], set_[64], red[4];
    float ei = img_ui[(size_t)r * 64 + d];
    float et = txt_ui[(size_t)r * 64 + d];
    sei[d]  = ei;
    set_[d] = et;
    __syncthreads();

    float bb = __ldg(&b1[d]);
    float hi = bb, ht = bb;
#pragma unroll 8
    for (int k = 0; k < 64; k++) {
        float w = __ldg(&W1[k * 64 + d]);
        hi += sei[k] * w;
        ht += set_[k] * w;
    }
    float w2d = __ldg(&w2[d]);
    hi = lrelu(hi) * w2d;
    ht = lrelu(ht) * w2d;
#pragma unroll
    for (int o = 16; o; o >>= 1) {
        hi += __shfl_down_sync(0xffffffffu, hi, o);
        ht += __shfl_down_sync(0xffffffffu, ht, o);
    }
    int wlane = d & 31, wid = d >> 5;
    if (wlane == 0) { red[wid] = hi; red[2 + wid] = ht; }
    __syncthreads();
    float s_img = red[0] + red[1];
    float s_txt = red[2] + red[3];
    float w0 = 1.f / (1.f + __expf(s_txt - s_img));   // softmax over 2 -> weight of img
    float common = w0 * ei + (1.f - w0) * et;

    size_t base = (size_t)r * 64 + d;
    out[(size_t)1 * NN * DD + base] = ei - common;   // special_img
    out[(size_t)2 * NN * DD + base] = et - common;   // special_txt
    out[(size_t)3 * NN * DD + base] = common;        // common
}

// ---------------- driver ------------------------------------------------------
static inline int g16(int n) { return (n + 255) / 256; }

extern "C" void kernel_launch(void* const* d_in, const int* in_sizes, int n_in,
                              void* d_out, int out_size) {
    const float* user_emb  = (const float*)d_in[0];
    const float* item_emb  = (const float*)d_in[1];
    const float* image_emb = (const float*)d_in[2];
    const float* text_emb  = (const float*)d_in[3];
    const float* W_img = (const float*)d_in[4];
    const float* b_img = (const float*)d_in[5];
    const float* bng_img = (const float*)d_in[6];
    const float* bnb_img = (const float*)d_in[7];
    const float* W_txt = (const float*)d_in[8];
    const float* b_txt = (const float*)d_in[9];
    const float* bng_txt = (const float*)d_in[10];
    const float* bnb_txt = (const float*)d_in[11];
    const float* W_gi = (const float*)d_in[12];
    const float* b_gi = (const float*)d_in[13];
    const float* W_gt = (const float*)d_in[14];
    const float* b_gt = (const float*)d_in[15];
    const float* W_c1 = (const float*)d_in[16];
    const float* b_c1 = (const float*)d_in[17];
    const float* w_c2 = (const float*)d_in[18];
    const float* ui_vals = (const float*)d_in[19];
    const float* R_vals  = (const float*)d_in[20];
    const float* ii_i_vals = (const float*)d_in[21];
    const float* ii_t_vals = (const float*)d_in[22];
    const int* ui_rows = (const int*)d_in[23];
    const int* ui_cols = (const int*)d_in[24];
    const int* R_rows  = (const int*)d_in[25];
    const int* R_cols  = (const int*)d_in[26];
    const int* ii_i_rows = (const int*)d_in[27];
    const int* ii_i_cols = (const int*)d_in[28];
    const int* ii_t_rows = (const int*)d_in[29];
    const int* ii_t_cols = (const int*)d_in[30];

    float* out = (float*)d_out;

    void* p;
    cudaGetSymbolAddress(&p, g_cat0);   float* cat0   = (float*)p;
    cudaGetSymbolAddress(&p, g_cat1);   float* cat1   = (float*)p;
    cudaGetSymbolAddress(&p, g_cat2);   float* cat2   = (float*)p;
    cudaGetSymbolAddress(&p, g_img_ui); float* img_ui = (float*)p;
    cudaGetSymbolAddress(&p, g_txt_ui); float* txt_ui = (float*)p;
    cudaGetSymbolAddress(&p, g_tmp0);   float* tmp0   = (float*)p;
    cudaGetSymbolAddress(&p, g_tmp1);   float* tmp1   = (float*)p;
    cudaGetSymbolAddress(&p, g_feat);   float* feat   = (float*)p;

    const int NN4 = NN * DD / 4;   // 1,280,000
    const int NI4 = NI * DD / 4;   //   480,000
    const int NU4 = NU * DD / 4;   //   800,000

    // ---- user-item GCN: cat = [item_emb ; user_emb] ----
    copy_kernel<<<g16(NI4), 256>>>(cat0, item_emb, NI4);
    copy_kernel<<<g16(NU4), 256>>>(cat0 + (size_t)NI * DD, user_emb, NU4);

    zero_kernel<<<g16(NN4), 256>>>(cat1, NN4);
    spmm_kernel<<<g16(NNZ_UI * 16), 256>>>(ui_rows, ui_cols, ui_vals, cat0, cat1, NNZ_UI);
    zero_kernel<<<g16(NN4), 256>>>(cat2, NN4);
    spmm_kernel<<<g16(NNZ_UI * 16), 256>>>(ui_rows, ui_cols, ui_vals, cat1, cat2, NNZ_UI);
    mean3_kernel<<<g16(NN4), 256>>>(cat0, cat1, cat2, out, NN4);   // out[0] = content

    // ---- image branch ----
    proj_kernel<512><<<(NI + 31) / 32, 256>>>(image_emb, W_img, b_img, bng_img, bnb_img, feat);
    gate_kernel<<<NI, 64>>>(feat, item_emb, W_gi, b_gi, tmp0);
    zero_kernel<<<g16(NI4), 256>>>(tmp1, NI4);
    spmm_kernel<<<g16(NNZ_II * 16), 256>>>(ii_i_rows, ii_i_cols, ii_i_vals, tmp0, tmp1, NNZ_II);
    zero_kernel<<<g16(NI4), 256>>>(tmp0, NI4);
    spmm_kernel<<<g16(NNZ_II * 16), 256>>>(ii_i_rows, ii_i_cols, ii_i_vals, tmp1, tmp0, NNZ_II);
    zero_kernel<<<g16(NU4), 256>>>(img_ui, NU4);
    spmm_kernel<<<g16(NNZ_R * 16), 256>>>(R_rows, R_cols, R_vals, tmp0, img_ui, NNZ_R);
    copy_kernel<<<g16(NI4), 256>>>(img_ui + (size_t)NU * DD, tmp0, NI4);

    // ---- text branch ----
    proj_kernel<384><<<(NI + 31) / 32, 256>>>(text_emb, W_txt, b_txt, bng_txt, bnb_txt, feat);
    gate_kernel<<<NI, 64>>>(feat, item_emb, W_gt, b_gt, tmp0);
    zero_kernel<<<g16(NI4), 256>>>(tmp1, NI4);
    spmm_kernel<<<g16(NNZ_II * 16), 256>>>(ii_t_rows, ii_t_cols, ii_t_vals, tmp0, tmp1, NNZ_II);
    zero_kernel<<<g16(NI4), 256>>>(tmp0, NI4);
    spmm_kernel<<<g16(NNZ_II * 16), 256>>>(ii_t_rows, ii_t_cols, ii_t_vals, tmp1, tmp0, NNZ_II);
    zero_kernel<<<g16(NU4), 256>>>(txt_ui, NU4);
    spmm_kernel<<<g16(NNZ_R * 16), 256>>>(R_rows, R_cols, R_vals, tmp0, txt_ui, NNZ_R);
    copy_kernel<<<g16(NI4), 256>>>(txt_ui + (size_t)NU * DD, tmp0, NI4);

    // ---- attention fusion -> out[1], out[2], out[3] ----
    att_fuse_kernel<<<NN, 64>>>(img_ui, txt_ui, W_c1, b_c1, w_c2, out);
}

// round 2
// speedup vs baseline: 1.0165x; 1.0165x over previous
#include <cuda_runtime.h>
#include <math.h>

#define NU 50000
#define NI 30000
#define NN 80000
#define DD 64

#define NNZ_UI 1000000
#define NNZ_R  800000
#define NNZ_II 300000

// ---------------- scratch (static device globals; no allocs allowed) ----------
__device__ float g_cat0[NN * DD];
__device__ float g_cat1[NN * DD];
__device__ float g_cat2[NN * DD];
__device__ float g_img_ui[NN * DD];
__device__ float g_txt_ui[NN * DD];
__device__ float g_gi0[NI * DD];
__device__ float g_gi1[NI * DD];
__device__ float g_gt0[NI * DD];
__device__ float g_gt1[NI * DD];
__device__ float g_feat[NI * DD];

__device__ __forceinline__ float lrelu(float x) { return x >= 0.f ? x : 0.01f * x; }

__device__ __forceinline__ void red4(float* dst, float v, float4 x) {
    asm volatile("red.global.add.v4.f32 [%0], {%1, %2, %3, %4};"
                 :: "l"(dst), "f"(v * x.x), "f"(v * x.y), "f"(v * x.z), "f"(v * x.w)
                 : "memory");
}

// ---------------- fused prep: all copies + zeros in one pass ------------------
__global__ void prep_kernel(const float* __restrict__ item_emb, const float* __restrict__ user_emb,
                            float* __restrict__ cat0, float* __restrict__ cat1,
                            float* __restrict__ cat2, float* __restrict__ gi1,
                            float* __restrict__ gt1, float* __restrict__ img_ui,
                            float* __restrict__ txt_ui) {
    const int NI4 = NI * 16, NU4 = NU * 16, NN4 = NN * 16;
    int i = blockIdx.x * blockDim.x + threadIdx.x;
    float4 z = make_float4(0.f, 0.f, 0.f, 0.f);
    if (i < NI4) { ((float4*)cat0)[i] = ((const float4*)item_emb)[i]; return; }
    i -= NI4;
    if (i < NU4) { ((float4*)cat0)[NI4 + i] = ((const float4*)user_emb)[i]; return; }
    i -= NU4;
    if (i < NN4) { ((float4*)cat1)[i] = z; return; }
    i -= NN4;
    if (i < NN4) { ((float4*)cat2)[i] = z; return; }
    i -= NN4;
    if (i < NN4) { ((float4*)img_ui)[i] = z; return; }
    i -= NN4;
    if (i < NN4) { ((float4*)txt_ui)[i] = z; return; }
    i -= NN4;
    if (i < NI4) { ((float4*)gi1)[i] = z; return; }
    i -= NI4;
    if (i < NI4) { ((float4*)gt1)[i] = z; return; }
}

__global__ void mean3_kernel(const float* __restrict__ a, const float* __restrict__ b,
                             const float* __restrict__ c, float* __restrict__ out, int n4) {
    int i = blockIdx.x * blockDim.x + threadIdx.x;
    if (i >= n4) return;
    float4 A = reinterpret_cast<const float4*>(a)[i];
    float4 B = reinterpret_cast<const float4*>(b)[i];
    float4 C = reinterpret_cast<const float4*>(c)[i];
    const float s = 1.f / 3.f;
    reinterpret_cast<float4*>(out)[i] =
        make_float4((A.x + B.x + C.x) * s, (A.y + B.y + C.y) * s,
                    (A.z + B.z + C.z) * s, (A.w + B.w + C.w) * s);
}

// ---------------- SpMM: out[rows[e]] += vals[e] * x[cols[e]] ------------------
// 2 edges per thread (MLP=2), 16 threads per edge (one float4 each).
__global__ void spmm2_kernel(const int* __restrict__ rows, const int* __restrict__ cols,
                             const float* __restrict__ vals, const float* __restrict__ x,
                             float* __restrict__ out, int nnz) {
    int t = blockIdx.x * blockDim.x + threadIdx.x;
    int j = t & 15;
    int e0 = (t >> 4) * 2;
    if (e0 >= nnz) return;
    int e1 = e0 + 1;
    bool has1 = e1 < nnz;

    int c0 = __ldg(&cols[e0]);
    int c1 = has1 ? __ldg(&cols[e1]) : c0;
    float4 x0 = __ldg(reinterpret_cast<const float4*>(x) + (size_t)c0 * 16 + j);
    float4 x1 = __ldg(reinterpret_cast<const float4*>(x) + (size_t)c1 * 16 + j);
    int r0 = __ldg(&rows[e0]);
    float v0 = __ldg(&vals[e0]);
    red4(out + (size_t)r0 * 64 + j * 4, v0, x0);
    if (has1) {
        int r1 = __ldg(&rows[e1]);
        float v1 = __ldg(&vals[e1]);
        red4(out + (size_t)r1 * 64 + j * 4, v1, x1);
    }
}

// ---------------- projection GEMM + BN + leaky_relu ---------------------------
template <int F>
__global__ void proj_kernel(const float* __restrict__ x, const float* __restrict__ W,
                            const float* __restrict__ b, const float* __restrict__ g,
                            const float* __restrict__ beta, float* __restrict__ out) {
    __shared__ float  sX[32][68];
    __shared__ float4 sW[64][16];

    int tid = threadIdx.x;
    int cg  = tid & 7;
    int row = tid >> 3;
    int r0  = blockIdx.x * 32;

    float acc[8];
#pragma unroll
    for (int i = 0; i < 8; i++) acc[i] = 0.f;

    for (int kc = 0; kc < F; kc += 64) {
        {
            int lr = tid >> 3;
            int lc = (tid & 7) * 8;
            int gr = r0 + lr;
            float4 a = make_float4(0.f, 0.f, 0.f, 0.f), bb = a;
            if (gr < NI) {
                const float* src = x + (size_t)gr * F + kc + lc;
                a  = *reinterpret_cast<const float4*>(src);
                bb = *reinterpret_cast<const float4*>(src + 4);
            }
            *reinterpret_cast<float4*>(&sX[lr][lc])     = a;
            *reinterpret_cast<float4*>(&sX[lr][lc + 4]) = bb;
        }
#pragma unroll
        for (int i = 0; i < 4; i++) {
            int idx = tid + i * 256;
            int wk  = idx >> 4;
            int wc  = idx & 15;
            sW[wk][wc] = *reinterpret_cast<const float4*>(&W[(size_t)(kc + wk) * 64 + wc * 4]);
        }
        __syncthreads();

#pragma unroll
        for (int k = 0; k < 64; k++) {
            float  xv = sX[row][k];
            float4 w0 = sW[k][cg * 2];
            float4 w1 = sW[k][cg * 2 + 1];
            acc[0] += xv * w0.x; acc[1] += xv * w0.y; acc[2] += xv * w0.z; acc[3] += xv * w0.w;
            acc[4] += xv * w1.x; acc[5] += xv * w1.y; acc[6] += xv * w1.z; acc[7] += xv * w1.w;
        }
        __syncthreads();
    }

    int r = r0 + row;
    if (r < NI) {
        const float rs = rsqrtf(1.f + 1e-5f);
        int dbase = cg * 8;
#pragma unroll
        for (int j = 0; j < 8; j++) {
            int d = dbase + j;
            float v = acc[j] + __ldg(&b[d]);
            v = v * (__ldg(&g[d]) * rs) + __ldg(&beta[d]);
            out[(size_t)r * 64 + d] = lrelu(v);
        }
    }
}

// ---------------- gate: out[r,d] = item_emb[r,d]*sigmoid(feat[r,:]@Wg[:,d]+bg[d])
// 256 threads = 4 rows x 64 cols; W column register-cached; 128 rows per block.
__global__ __launch_bounds__(256, 2)
void gate_kernel(const float* __restrict__ feat, const float* __restrict__ item_emb,
                 const float* __restrict__ Wg, const float* __restrict__ bg,
                 float* __restrict__ out) {
    __shared__ float sf[4][64];
    int d   = threadIdx.x & 63;
    int sub = threadIdx.x >> 6;

    float Wc[64];
#pragma unroll
    for (int k = 0; k < 64; k++) Wc[k] = __ldg(&Wg[k * 64 + d]);
    float bgd = __ldg(&bg[d]);

    int r0 = blockIdx.x * 128;
#pragma unroll 1
    for (int i = 0; i < 32; i++) {
        int r = r0 + i * 4 + sub;
        float fv = (r < NI) ? feat[(size_t)r * 64 + d] : 0.f;
        sf[sub][d] = fv;
        __syncthreads();
        float acc = bgd;
#pragma unroll
        for (int k = 0; k < 64; k += 4) {
            float4 a = *reinterpret_cast<const float4*>(&sf[sub][k]);
            acc += a.x * Wc[k] + a.y * Wc[k + 1] + a.z * Wc[k + 2] + a.w * Wc[k + 3];
        }
        if (r < NI) {
            float sig = 1.f / (1.f + __expf(-acc));
            out[(size_t)r * 64 + d] = item_emb[(size_t)r * 64 + d] * sig;
        }
        __syncthreads();
    }
}

// ---------------- attention fusion (writes out[1..3]) -------------------------
// 256 threads = 4 rows x 64 cols; W1 column register-cached; 128 rows per block.
__global__ __launch_bounds__(256, 2)
void att_kernel(const float* __restrict__ img_ui, const float* __restrict__ txt_ui,
                const float* __restrict__ W1, const float* __restrict__ b1,
                const float* __restrict__ w2, float* __restrict__ out) {
    __shared__ float sei[4][64], set_[4][64];
    __shared__ float wsum[8][2];
    int d    = threadIdx.x & 63;
    int sub  = threadIdx.x >> 6;
    int warp = threadIdx.x >> 5;
    int lane = threadIdx.x & 31;

    float Wc[64];
#pragma unroll
    for (int k = 0; k < 64; k++) Wc[k] = __ldg(&W1[k * 64 + d]);
    float b1d = __ldg(&b1[d]);
    float w2d = __ldg(&w2[d]);

    int r0 = blockIdx.x * 128;
#pragma unroll 1
    for (int i = 0; i < 32; i++) {
        int r = r0 + i * 4 + sub;            // NN = 625*128 exactly -> always valid
        size_t base = (size_t)r * 64 + d;
        float ei = img_ui[base];
        float et = txt_ui[base];
        sei[sub][d]  = ei;
        set_[sub][d] = et;
        __syncthreads();

        float hi = b1d, ht = b1d;
#pragma unroll
        for (int k = 0; k < 64; k += 4) {
            float4 a = *reinterpret_cast<const float4*>(&sei[sub][k]);
            float4 b = *reinterpret_cast<const float4*>(&set_[sub][k]);
            hi += a.x * Wc[k] + a.y * Wc[k + 1] + a.z * Wc[k + 2] + a.w * Wc[k + 3];
            ht += b.x * Wc[k] + b.y * Wc[k + 1] + b.z * Wc[k + 2] + b.w * Wc[k + 3];
        }
        hi = lrelu(hi) * w2d;
        ht = lrelu(ht) * w2d;
#pragma unroll
        for (int o = 16; o; o >>= 1) {
            hi += __shfl_xor_sync(0xffffffffu, hi, o);
            ht += __shfl_xor_sync(0xffffffffu, ht, o);
        }
        if (lane == 0) { wsum[warp][0] = hi; wsum[warp][1] = ht; }
        __syncthreads();
        int wbase = sub * 2;
        float si = wsum[wbase][0] + wsum[wbase + 1][0];
        float st = wsum[wbase][1] + wsum[wbase + 1][1];
        float wimg = 1.f / (1.f + __expf(st - si));
        float common = wimg * ei + (1.f - wimg) * et;

        out[(size_t)1 * NN * DD + base] = ei - common;
        out[(size_t)2 * NN * DD + base] = et - common;
        out[(size_t)3 * NN * DD + base] = common;
        __syncthreads();
    }
}

// ---------------- driver ------------------------------------------------------
static inline int g256(long long n) { return (int)((n + 255) / 256); }

extern "C" void kernel_launch(void* const* d_in, const int* in_sizes, int n_in,
                              void* d_out, int out_size) {
    const float* user_emb  = (const float*)d_in[0];
    const float* item_emb  = (const float*)d_in[1];
    const float* image_emb = (const float*)d_in[2];
    const float* text_emb  = (const float*)d_in[3];
    const float* W_img = (const float*)d_in[4];
    const float* b_img = (const float*)d_in[5];
    const float* bng_img = (const float*)d_in[6];
    const float* bnb_img = (const float*)d_in[7];
    const float* W_txt = (const float*)d_in[8];
    const float* b_txt = (const float*)d_in[9];
    const float* bng_txt = (const float*)d_in[10];
    const float* bnb_txt = (const float*)d_in[11];
    const float* W_gi = (const float*)d_in[12];
    const float* b_gi = (const float*)d_in[13];
    const float* W_gt = (const float*)d_in[14];
    const float* b_gt = (const float*)d_in[15];
    const float* W_c1 = (const float*)d_in[16];
    const float* b_c1 = (const float*)d_in[17];
    const float* w_c2 = (const float*)d_in[18];
    const float* ui_vals = (const float*)d_in[19];
    const float* R_vals  = (const float*)d_in[20];
    const float* ii_i_vals = (const float*)d_in[21];
    const float* ii_t_vals = (const float*)d_in[22];
    const int* ui_rows = (const int*)d_in[23];
    const int* ui_cols = (const int*)d_in[24];
    const int* R_rows  = (const int*)d_in[25];
    const int* R_cols  = (const int*)d_in[26];
    const int* ii_i_rows = (const int*)d_in[27];
    const int* ii_i_cols = (const int*)d_in[28];
    const int* ii_t_rows = (const int*)d_in[29];
    const int* ii_t_cols = (const int*)d_in[30];

    float* out = (float*)d_out;

    void* p;
    cudaGetSymbolAddress(&p, g_cat0);   float* cat0   = (float*)p;
    cudaGetSymbolAddress(&p, g_cat1);   float* cat1   = (float*)p;
    cudaGetSymbolAddress(&p, g_cat2);   float* cat2   = (float*)p;
    cudaGetSymbolAddress(&p, g_img_ui); float* img_ui = (float*)p;
    cudaGetSymbolAddress(&p, g_txt_ui); float* txt_ui = (float*)p;
    cudaGetSymbolAddress(&p, g_gi0);    float* gi0    = (float*)p;
    cudaGetSymbolAddress(&p, g_gi1);    float* gi1    = (float*)p;
    cudaGetSymbolAddress(&p, g_gt0);    float* gt0    = (float*)p;
    cudaGetSymbolAddress(&p, g_gt1);    float* gt1    = (float*)p;
    cudaGetSymbolAddress(&p, g_feat);   float* feat   = (float*)p;

    float* img_items = img_ui + (size_t)NU * DD;
    float* txt_items = txt_ui + (size_t)NU * DD;

    const long long PREP_N = (long long)NI * 16 + (long long)NU * 16 +
                             4LL * NN * 16 + 2LL * NI * 16;   // 7,360,000 float4
    const int NN4 = NN * 16;

    // spmm2 grid: (nnz/2 edge-pairs) * 16 threads
    const int G_UI = NNZ_UI / 32;   // 31250
    const int G_II = NNZ_II / 32;   //  9375
    const int G_R  = NNZ_R  / 32;   // 25000

    // 1. prep: cat0 = [item;user], zero cat1/cat2/img_ui/txt_ui/gi1/gt1
    prep_kernel<<<g256(PREP_N), 256>>>(item_emb, user_emb, cat0, cat1, cat2,
                                       gi1, gt1, img_ui, txt_ui);

    // 2. user-item GCN
    spmm2_kernel<<<G_UI, 256>>>(ui_rows, ui_cols, ui_vals, cat0, cat1, NNZ_UI);
    spmm2_kernel<<<G_UI, 256>>>(ui_rows, ui_cols, ui_vals, cat1, cat2, NNZ_UI);
    mean3_kernel<<<g256(NN4), 256>>>(cat0, cat1, cat2, out, NN4);   // out[0]

    // 3. projections + gates
    proj_kernel<512><<<(NI + 31) / 32, 256>>>(image_emb, W_img, b_img, bng_img, bnb_img, feat);
    gate_kernel<<<(NI + 127) / 128, 256>>>(feat, item_emb, W_gi, b_gi, gi0);
    proj_kernel<384><<<(NI + 31) / 32, 256>>>(text_emb, W_txt, b_txt, bng_txt, bnb_txt, feat);
    gate_kernel<<<(NI + 127) / 128, 256>>>(feat, item_emb, W_gt, b_gt, gt0);

    // 4. item-item GCNs (2nd hop writes directly into the item region of *_ui)
    spmm2_kernel<<<G_II, 256>>>(ii_i_rows, ii_i_cols, ii_i_vals, gi0, gi1, NNZ_II);
    spmm2_kernel<<<G_II, 256>>>(ii_i_rows, ii_i_cols, ii_i_vals, gi1, img_items, NNZ_II);
    spmm2_kernel<<<G_II, 256>>>(ii_t_rows, ii_t_cols, ii_t_vals, gt0, gt1, NNZ_II);
    spmm2_kernel<<<G_II, 256>>>(ii_t_rows, ii_t_cols, ii_t_vals, gt1, txt_items, NNZ_II);

    // 5. R @ items -> user region of *_ui
    spmm2_kernel<<<G_R, 256>>>(R_rows, R_cols, R_vals, img_items, img_ui, NNZ_R);
    spmm2_kernel<<<G_R, 256>>>(R_rows, R_cols, R_vals, txt_items, txt_ui, NNZ_R);

    // 6. attention fusion -> out[1..3]
    att_kernel<<<NN / 128, 256>>>(img_ui, txt_ui, W_c1, b_c1, w_c2, out);
}

// round 3
// speedup vs baseline: 1.1222x; 1.1041x over previous
#include <cuda_runtime.h>
#include <math.h>

#define NU 50000
#define NI 30000
#define NN 80000
#define DD 64

#define NNZ_UI 1000000
#define NNZ_R  800000
#define NNZ_II 300000

// ---------------- scratch (static device globals; no allocs allowed) ----------
__device__ float g_cat0[NN * DD];
__device__ float g_cat1[NN * DD];
__device__ float g_cat2[NN * DD];
__device__ float g_img_ui[NN * DD];
__device__ float g_txt_ui[NN * DD];
__device__ float g_gi0[NI * DD];
__device__ float g_gi1[NI * DD];
__device__ float g_gt0[NI * DD];
__device__ float g_gt1[NI * DD];
__device__ float g_feat_i[NI * DD];
__device__ float g_feat_t[NI * DD];

__device__ __forceinline__ float lrelu(float x) { return x >= 0.f ? x : 0.01f * x; }

__device__ __forceinline__ void red4(float* dst, float v, float4 x) {
    asm volatile("red.global.add.v4.f32 [%0], {%1, %2, %3, %4};"
                 :: "l"(dst), "f"(v * x.x), "f"(v * x.y), "f"(v * x.z), "f"(v * x.w)
                 : "memory");
}

// ---------------- fused prep: all copies + zeros in one pass ------------------
__global__ void prep_kernel(const float* __restrict__ item_emb, const float* __restrict__ user_emb,
                            float* __restrict__ cat0, float* __restrict__ cat1,
                            float* __restrict__ cat2, float* __restrict__ gi1,
                            float* __restrict__ gt1, float* __restrict__ img_ui,
                            float* __restrict__ txt_ui) {
    const int NI4 = NI * 16, NU4 = NU * 16, NN4 = NN * 16;
    int i = blockIdx.x * blockDim.x + threadIdx.x;
    float4 z = make_float4(0.f, 0.f, 0.f, 0.f);
    if (i < NI4) { ((float4*)cat0)[i] = ((const float4*)item_emb)[i]; return; }
    i -= NI4;
    if (i < NU4) { ((float4*)cat0)[NI4 + i] = ((const float4*)user_emb)[i]; return; }
    i -= NU4;
    if (i < NN4) { ((float4*)cat1)[i] = z; return; }
    i -= NN4;
    if (i < NN4) { ((float4*)cat2)[i] = z; return; }
    i -= NN4;
    if (i < NN4) { ((float4*)img_ui)[i] = z; return; }
    i -= NN4;
    if (i < NN4) { ((float4*)txt_ui)[i] = z; return; }
    i -= NN4;
    if (i < NI4) { ((float4*)gi1)[i] = z; return; }
    i -= NI4;
    if (i < NI4) { ((float4*)gt1)[i] = z; return; }
}

__global__ void mean3_kernel(const float* __restrict__ a, const float* __restrict__ b,
                             const float* __restrict__ c, float* __restrict__ out, int n4) {
    int i = blockIdx.x * blockDim.x + threadIdx.x;
    if (i >= n4) return;
    float4 A = reinterpret_cast<const float4*>(a)[i];
    float4 B = reinterpret_cast<const float4*>(b)[i];
    float4 C = reinterpret_cast<const float4*>(c)[i];
    const float s = 1.f / 3.f;
    reinterpret_cast<float4*>(out)[i] =
        make_float4((A.x + B.x + C.x) * s, (A.y + B.y + C.y) * s,
                    (A.z + B.z + C.z) * s, (A.w + B.w + C.w) * s);
}

// ---------------- SpMM: out[rows[e]] += vals[e] * x[cols[e]] ------------------
__global__ void spmm2_kernel(const int* __restrict__ rows, const int* __restrict__ cols,
                             const float* __restrict__ vals, const float* __restrict__ x,
                             float* __restrict__ out, int nnz) {
    int t = blockIdx.x * blockDim.x + threadIdx.x;
    int j = t & 15;
    int e0 = (t >> 4) * 2;
    if (e0 >= nnz) return;
    int e1 = e0 + 1;
    bool has1 = e1 < nnz;

    int c0 = __ldg(&cols[e0]);
    int c1 = has1 ? __ldg(&cols[e1]) : c0;
    float4 x0 = __ldg(reinterpret_cast<const float4*>(x) + (size_t)c0 * 16 + j);
    float4 x1 = __ldg(reinterpret_cast<const float4*>(x) + (size_t)c1 * 16 + j);
    int r0 = __ldg(&rows[e0]);
    float v0 = __ldg(&vals[e0]);
    red4(out + (size_t)r0 * 64 + j * 4, v0, x0);
    if (has1) {
        int r1 = __ldg(&rows[e1]);
        float v1 = __ldg(&vals[e1]);
        red4(out + (size_t)r1 * 64 + j * 4, v1, x1);
    }
}

// ---------------- projection GEMM + BN + leaky_relu ---------------------------
template <int F>
__global__ void proj_kernel(const float* __restrict__ x, const float* __restrict__ W,
                            const float* __restrict__ b, const float* __restrict__ g,
                            const float* __restrict__ beta, float* __restrict__ out) {
    __shared__ float  sX[32][68];
    __shared__ float4 sW[64][16];

    int tid = threadIdx.x;
    int cg  = tid & 7;
    int row = tid >> 3;
    int r0  = blockIdx.x * 32;

    float acc[8];
#pragma unroll
    for (int i = 0; i < 8; i++) acc[i] = 0.f;

    for (int kc = 0; kc < F; kc += 64) {
        {
            int lr = tid >> 3;
            int lc = (tid & 7) * 8;
            int gr = r0 + lr;
            float4 a = make_float4(0.f, 0.f, 0.f, 0.f), bb = a;
            if (gr < NI) {
                const float* src = x + (size_t)gr * F + kc + lc;
                a  = *reinterpret_cast<const float4*>(src);
                bb = *reinterpret_cast<const float4*>(src + 4);
            }
            *reinterpret_cast<float4*>(&sX[lr][lc])     = a;
            *reinterpret_cast<float4*>(&sX[lr][lc + 4]) = bb;
        }
#pragma unroll
        for (int i = 0; i < 4; i++) {
            int idx = tid + i * 256;
            int wk  = idx >> 4;
            int wc  = idx & 15;
            sW[wk][wc] = *reinterpret_cast<const float4*>(&W[(size_t)(kc + wk) * 64 + wc * 4]);
        }
        __syncthreads();

#pragma unroll
        for (int k = 0; k < 64; k++) {
            float  xv = sX[row][k];
            float4 w0 = sW[k][cg * 2];
            float4 w1 = sW[k][cg * 2 + 1];
            acc[0] += xv * w0.x; acc[1] += xv * w0.y; acc[2] += xv * w0.z; acc[3] += xv * w0.w;
            acc[4] += xv * w1.x; acc[5] += xv * w1.y; acc[6] += xv * w1.z; acc[7] += xv * w1.w;
        }
        __syncthreads();
    }

    int r = r0 + row;
    if (r < NI) {
        const float rs = rsqrtf(1.f + 1e-5f);
        int dbase = cg * 8;
#pragma unroll
        for (int j = 0; j < 8; j++) {
            int d = dbase + j;
            float v = acc[j] + __ldg(&b[d]);
            v = v * (__ldg(&g[d]) * rs) + __ldg(&beta[d]);
            out[(size_t)r * 64 + d] = lrelu(v);
        }
    }
}

// ---------------- gate ---------------------------------------------------------
__global__ __launch_bounds__(256, 2)
void gate_kernel(const float* __restrict__ feat, const float* __restrict__ item_emb,
                 const float* __restrict__ Wg, const float* __restrict__ bg,
                 float* __restrict__ out) {
    __shared__ float sf[4][64];
    int d   = threadIdx.x & 63;
    int sub = threadIdx.x >> 6;

    float Wc[64];
#pragma unroll
    for (int k = 0; k < 64; k++) Wc[k] = __ldg(&Wg[k * 64 + d]);
    float bgd = __ldg(&bg[d]);

    int r0 = blockIdx.x * 128;
#pragma unroll 1
    for (int i = 0; i < 32; i++) {
        int r = r0 + i * 4 + sub;
        float fv = (r < NI) ? feat[(size_t)r * 64 + d] : 0.f;
        sf[sub][d] = fv;
        __syncthreads();
        float acc = bgd;
#pragma unroll
        for (int k = 0; k < 64; k += 4) {
            float4 a = *reinterpret_cast<const float4*>(&sf[sub][k]);
            acc += a.x * Wc[k] + a.y * Wc[k + 1] + a.z * Wc[k + 2] + a.w * Wc[k + 3];
        }
        if (r < NI) {
            float sig = 1.f / (1.f + __expf(-acc));
            out[(size_t)r * 64 + d] = item_emb[(size_t)r * 64 + d] * sig;
        }
        __syncthreads();
    }
}

// ---------------- attention fusion (writes out[1..3]) -------------------------
__global__ __launch_bounds__(256, 2)
void att_kernel(const float* __restrict__ img_ui, const float* __restrict__ txt_ui,
                const float* __restrict__ W1, const float* __restrict__ b1,
                const float* __restrict__ w2, float* __restrict__ out) {
    __shared__ float sei[4][64], set_[4][64];
    __shared__ float wsum[8][2];
    int d    = threadIdx.x & 63;
    int sub  = threadIdx.x >> 6;
    int warp = threadIdx.x >> 5;
    int lane = threadIdx.x & 31;

    float Wc[64];
#pragma unroll
    for (int k = 0; k < 64; k++) Wc[k] = __ldg(&W1[k * 64 + d]);
    float b1d = __ldg(&b1[d]);
    float w2d = __ldg(&w2[d]);

    int r0 = blockIdx.x * 128;
#pragma unroll 1
    for (int i = 0; i < 32; i++) {
        int r = r0 + i * 4 + sub;
        size_t base = (size_t)r * 64 + d;
        float ei = img_ui[base];
        float et = txt_ui[base];
        sei[sub][d]  = ei;
        set_[sub][d] = et;
        __syncthreads();

        float hi = b1d, ht = b1d;
#pragma unroll
        for (int k = 0; k < 64; k += 4) {
            float4 a = *reinterpret_cast<const float4*>(&sei[sub][k]);
            float4 b = *reinterpret_cast<const float4*>(&set_[sub][k]);
            hi += a.x * Wc[k] + a.y * Wc[k + 1] + a.z * Wc[k + 2] + a.w * Wc[k + 3];
            ht += b.x * Wc[k] + b.y * Wc[k + 1] + b.z * Wc[k + 2] + b.w * Wc[k + 3];
        }
        hi = lrelu(hi) * w2d;
        ht = lrelu(ht) * w2d;
#pragma unroll
        for (int o = 16; o; o >>= 1) {
            hi += __shfl_xor_sync(0xffffffffu, hi, o);
            ht += __shfl_xor_sync(0xffffffffu, ht, o);
        }
        if (lane == 0) { wsum[warp][0] = hi; wsum[warp][1] = ht; }
        __syncthreads();
        int wbase = sub * 2;
        float si = wsum[wbase][0] + wsum[wbase + 1][0];
        float st = wsum[wbase][1] + wsum[wbase + 1][1];
        float wimg = 1.f / (1.f + __expf(st - si));
        float common = wimg * ei + (1.f - wimg) * et;

        out[(size_t)1 * NN * DD + base] = ei - common;
        out[(size_t)2 * NN * DD + base] = et - common;
        out[(size_t)3 * NN * DD + base] = common;
        __syncthreads();
    }
}

// ---------------- driver ------------------------------------------------------
static inline int g256(long long n) { return (int)((n + 255) / 256); }

extern "C" void kernel_launch(void* const* d_in, const int* in_sizes, int n_in,
                              void* d_out, int out_size) {
    const float* user_emb  = (const float*)d_in[0];
    const float* item_emb  = (const float*)d_in[1];
    const float* image_emb = (const float*)d_in[2];
    const float* text_emb  = (const float*)d_in[3];
    const float* W_img = (const float*)d_in[4];
    const float* b_img = (const float*)d_in[5];
    const float* bng_img = (const float*)d_in[6];
    const float* bnb_img = (const float*)d_in[7];
    const float* W_txt = (const float*)d_in[8];
    const float* b_txt = (const float*)d_in[9];
    const float* bng_txt = (const float*)d_in[10];
    const float* bnb_txt = (const float*)d_in[11];
    const float* W_gi = (const float*)d_in[12];
    const float* b_gi = (const float*)d_in[13];
    const float* W_gt = (const float*)d_in[14];
    const float* b_gt = (const float*)d_in[15];
    const float* W_c1 = (const float*)d_in[16];
    const float* b_c1 = (const float*)d_in[17];
    const float* w_c2 = (const float*)d_in[18];
    const float* ui_vals = (const float*)d_in[19];
    const float* R_vals  = (const float*)d_in[20];
    const float* ii_i_vals = (const float*)d_in[21];
    const float* ii_t_vals = (const float*)d_in[22];
    const int* ui_rows = (const int*)d_in[23];
    const int* ui_cols = (const int*)d_in[24];
    const int* R_rows  = (const int*)d_in[25];
    const int* R_cols  = (const int*)d_in[26];
    const int* ii_i_rows = (const int*)d_in[27];
    const int* ii_i_cols = (const int*)d_in[28];
    const int* ii_t_rows = (const int*)d_in[29];
    const int* ii_t_cols = (const int*)d_in[30];

    float* out = (float*)d_out;

    void* p;
    cudaGetSymbolAddress(&p, g_cat0);   float* cat0   = (float*)p;
    cudaGetSymbolAddress(&p, g_cat1);   float* cat1   = (float*)p;
    cudaGetSymbolAddress(&p, g_cat2);   float* cat2   = (float*)p;
    cudaGetSymbolAddress(&p, g_img_ui); float* img_ui = (float*)p;
    cudaGetSymbolAddress(&p, g_txt_ui); float* txt_ui = (float*)p;
    cudaGetSymbolAddress(&p, g_gi0);    float* gi0    = (float*)p;
    cudaGetSymbolAddress(&p, g_gi1);    float* gi1    = (float*)p;
    cudaGetSymbolAddress(&p, g_gt0);    float* gt0    = (float*)p;
    cudaGetSymbolAddress(&p, g_gt1);    float* gt1    = (float*)p;
    cudaGetSymbolAddress(&p, g_feat_i); float* feat_i = (float*)p;
    cudaGetSymbolAddress(&p, g_feat_t); float* feat_t = (float*)p;

    float* img_items = img_ui + (size_t)NU * DD;
    float* txt_items = txt_ui + (size_t)NU * DD;

    // --- lazily create side streams + fork/join events (once per process) ----
    static cudaStream_t sA = nullptr, sB = nullptr, sC = nullptr;
    static cudaEvent_t eFork = nullptr, eA = nullptr, eB = nullptr, eC = nullptr;
    if (!sA) {
        cudaStreamCreateWithFlags(&sA, cudaStreamNonBlocking);
        cudaStreamCreateWithFlags(&sB, cudaStreamNonBlocking);
        cudaStreamCreateWithFlags(&sC, cudaStreamNonBlocking);
        cudaEventCreateWithFlags(&eFork, cudaEventDisableTiming);
        cudaEventCreateWithFlags(&eA, cudaEventDisableTiming);
        cudaEventCreateWithFlags(&eB, cudaEventDisableTiming);
        cudaEventCreateWithFlags(&eC, cudaEventDisableTiming);
    }

    const long long PREP_N = (long long)NI * 16 + (long long)NU * 16 +
                             4LL * NN * 16 + 2LL * NI * 16;
    const int NN4 = NN * 16;
    const int G_UI = NNZ_UI / 32;
    const int G_II = NNZ_II / 32;
    const int G_R  = NNZ_R  / 32;

    // 1. prep on the capture (default) stream
    prep_kernel<<<g256(PREP_N), 256>>>(item_emb, user_emb, cat0, cat1, cat2,
                                       gi1, gt1, img_ui, txt_ui);
    cudaEventRecord(eFork, 0);
    cudaStreamWaitEvent(sA, eFork, 0);
    cudaStreamWaitEvent(sB, eFork, 0);
    cudaStreamWaitEvent(sC, eFork, 0);

    // 2. chain A: user-item GCN -> out[0]
    spmm2_kernel<<<G_UI, 256, 0, sA>>>(ui_rows, ui_cols, ui_vals, cat0, cat1, NNZ_UI);
    spmm2_kernel<<<G_UI, 256, 0, sA>>>(ui_rows, ui_cols, ui_vals, cat1, cat2, NNZ_UI);
    mean3_kernel<<<g256(NN4), 256, 0, sA>>>(cat0, cat1, cat2, out, NN4);
    cudaEventRecord(eA, sA);

    // 3. chain B: image branch
    proj_kernel<512><<<(NI + 31) / 32, 256, 0, sB>>>(image_emb, W_img, b_img, bng_img, bnb_img, feat_i);
    gate_kernel<<<(NI + 127) / 128, 256, 0, sB>>>(feat_i, item_emb, W_gi, b_gi, gi0);
    spmm2_kernel<<<G_II, 256, 0, sB>>>(ii_i_rows, ii_i_cols, ii_i_vals, gi0, gi1, NNZ_II);
    spmm2_kernel<<<G_II, 256, 0, sB>>>(ii_i_rows, ii_i_cols, ii_i_vals, gi1, img_items, NNZ_II);
    spmm2_kernel<<<G_R, 256, 0, sB>>>(R_rows, R_cols, R_vals, img_items, img_ui, NNZ_R);
    cudaEventRecord(eB, sB);

    // 4. chain C: text branch
    proj_kernel<384><<<(NI + 31) / 32, 256, 0, sC>>>(text_emb, W_txt, b_txt, bng_txt, bnb_txt, feat_t);
    gate_kernel<<<(NI + 127) / 128, 256, 0, sC>>>(feat_t, item_emb, W_gt, b_gt, gt0);
    spmm2_kernel<<<G_II, 256, 0, sC>>>(ii_t_rows, ii_t_cols, ii_t_vals, gt0, gt1, NNZ_II);
    spmm2_kernel<<<G_II, 256, 0, sC>>>(ii_t_rows, ii_t_cols, ii_t_vals, gt1, txt_items, NNZ_II);
    spmm2_kernel<<<G_R, 256, 0, sC>>>(R_rows, R_cols, R_vals, txt_items, txt_ui, NNZ_R);
    cudaEventRecord(eC, sC);

    // 5. join and fuse
    cudaStreamWaitEvent(0, eA, 0);
    cudaStreamWaitEvent(0, eB, 0);
    cudaStreamWaitEvent(0, eC, 0);
    att_kernel<<<NN / 128, 256>>>(img_ui, txt_ui, W_c1, b_c1, w_c2, out);
}